// round 3
// baseline (speedup 1.0000x reference)
#include <cuda_runtime.h>

#define N_S 50000
#define N_A 50000
#define E_A 800000
#define E_S 800000
#define HID 128
#define AGGA_C 20     // [sum_u(16), sum_pa(2), sum_dis(1), deg_a(1)]
#define AGGS_C 164    // [sum_x(32), sum_h(128), sum_ps(2), sum_dis(1), deg_s(1)]
#define KF 352        // folded feature width (padded)

// Scratch (allocation-free rule: __device__ globals)
__device__ float g_agg_a[N_S * AGGA_C];
__device__ float g_agg_s[N_S * AGGS_C];
__device__ float g_Wf[KF * HID];

__device__ __forceinline__ void red4(float* addr, float a, float b, float c, float d) {
    asm volatile("red.global.add.v4.f32 [%0], {%1,%2,%3,%4};"
                 :: "l"(addr), "f"(a), "f"(b), "f"(c), "f"(d) : "memory");
}

__global__ void zero_kernel() {
    const int total = N_S * AGGA_C + N_S * AGGS_C;
    for (int i = blockIdx.x * blockDim.x + threadIdx.x; i < total;
         i += gridDim.x * blockDim.x) {
        if (i < N_S * AGGA_C) g_agg_a[i] = 0.f;
        else                  g_agg_s[i - N_S * AGGA_C] = 0.f;
    }
}

// One thread per a2s edge: scatter-add [u(16), pa(2), dis, 1] into agg_a[dst]
__global__ void scatter_a2s(const float* __restrict__ u, const float* __restrict__ pa,
                            const float* __restrict__ dis,
                            const int* __restrict__ src, const int* __restrict__ dst) {
    int e = blockIdx.x * blockDim.x + threadIdx.x;
    if (e >= E_A) return;
    int s = src[e], d = dst[e];
    const float4* u4 = (const float4*)(u + s * 16);
    float* base = g_agg_a + d * AGGA_C;
    float4 v0 = u4[0], v1 = u4[1], v2 = u4[2], v3 = u4[3];
    red4(base +  0, v0.x, v0.y, v0.z, v0.w);
    red4(base +  4, v1.x, v1.y, v1.z, v1.w);
    red4(base +  8, v2.x, v2.y, v2.z, v2.w);
    red4(base + 12, v3.x, v3.y, v3.z, v3.w);
    float2 p = *(const float2*)(pa + s * 2);
    red4(base + 16, p.x, p.y, dis[e], 1.f);
}

// One warp per s2s edge: scatter-add [x(32), h(128), ps(2), dis, 1] into agg_s[dst]
__global__ void scatter_s2s(const float* __restrict__ x, const float* __restrict__ h,
                            const float* __restrict__ ps, const float* __restrict__ dis,
                            const int* __restrict__ src, const int* __restrict__ dst) {
    int gid = blockIdx.x * blockDim.x + threadIdx.x;
    int e = gid >> 5;
    int lane = gid & 31;
    if (e >= E_S) return;
    int s = src[e], d = dst[e];
    float* base = g_agg_s + d * AGGS_C;
    // groups 0..31 (g = lane): g<8 -> x, else -> h
    float4 v;
    if (lane < 8) v = *(const float4*)(x + s * 32 + lane * 4);
    else          v = *(const float4*)(h + s * 128 + (lane - 8) * 4);
    red4(base + lane * 4, v.x, v.y, v.z, v.w);
    // groups 32..40 (lanes 0..8)
    if (lane < 9) {
        int g = lane + 32;
        if (g < 40) {
            v = *(const float4*)(h + s * 128 + (g - 8) * 4);
            red4(base + g * 4, v.x, v.y, v.z, v.w);
        } else {
            float2 p = *(const float2*)(ps + s * 2);
            red4(base + 160, p.x, p.y, dis[e], 1.f);
        }
    }
}

// Build folded weight matrix g_Wf[352][128].
// Feature layout per node (K index):
//   0-1 ps | 2-129 h | 130-161 x | 162-180 agg_a[0..18] | 181 deg_a | 182-183 deg_a*ps
//   184-346 agg_s[0..162]/deg | 347 m | 348-349 m*ps | 350 const 1 | 351 pad 0
__global__ void fold_kernel(const float* __restrict__ Wu, const float* __restrict__ bu,
                            const float* __restrict__ Wx, const float* __restrict__ bx,
                            const float* __restrict__ Wupd, const float* __restrict__ bupd) {
    int r = blockIdx.x;       // 0..351
    int j = threadIdx.x;      // 0..127
    float outv;
    if (r < 130) {
        outv = Wupd[r * 128 + j];                    // ps + h direct
    } else if (r < 162) {
        outv = Wupd[(386 + r - 130) * 128 + j];      // x direct
    } else if (r < 184) {
        // fold through sum_u block: W_su = Wupd rows 130..257
        int i = r - 162;
        const float* v;
        if (i < 18)      v = Wu + i * 128;           // u rows 0-15, pa rows 16-17
        else if (i == 18) v = Wu + 20 * 128;         // dis row
        else if (i == 19) v = bu;                    // deg_a -> bias
        else              v = Wu + (i - 2) * 128;    // deg_a*ps -> ps_dst rows 18,19
        const float* Wsu = Wupd + 130 * 128;
        float acc = 0.f;
        for (int m = 0; m < 128; m++) acc += v[m] * Wsu[m * 128 + j];
        outv = acc;
    } else if (r < 350) {
        // fold through mean_x block: W_mx = Wupd rows 258..385
        int i = r - 184;
        const float* v;
        if (i < 162)      v = Wx + i * 128;          // x(0-31), h(32-159), ps_src(160-161)
        else if (i == 162) v = Wx + 164 * 128;       // dis row
        else if (i == 163) v = bx;                   // m -> bias
        else               v = Wx + (i - 2) * 128;   // m*ps -> ps_dst rows 162,163
        const float* Wmx = Wupd + 258 * 128;
        float acc = 0.f;
        for (int m = 0; m < 128; m++) acc += v[m] * Wmx[m * 128 + j];
        outv = acc;
    } else if (r == 350) {
        outv = bupd[j];
    } else {
        outv = 0.f;
    }
    g_Wf[r * 128 + j] = outv;
}

// Fused feature build + GEMM: out[50000,128] = F[50000,352] @ Wf[352,128]
// CTA: 32 nodes, 256 threads. c=tid&31 -> cols 4c..4c+3, r=tid>>5 (0..7) -> nodes 4r..4r+3
__global__ __launch_bounds__(256) void fused_gemm(
    const float* __restrict__ h, const float* __restrict__ x,
    const float* __restrict__ ps, float* __restrict__ out) {
    extern __shared__ float smem[];
    float* sFT = smem;               // [KF][36]  (k-major, padded row stride 36)
    float* sW  = smem + KF * 36;     // [32][128] one K-chunk of Wf
    int tid = threadIdx.x;
    int base = blockIdx.x * 32;

    // ---- Phase 1: build per-node features (transposed, k-major) ----
    for (int idx = tid; idx < 32 * KF; idx += 256) {
        int n = idx / KF;
        int k = idx - n * KF;
        int node = base + n;
        float val = 0.f;
        if (node < N_S) {
            if (k < 2)        val = ps[node * 2 + k];
            else if (k < 130) val = h[node * 128 + (k - 2)];
            else if (k < 162) val = x[node * 32 + (k - 130)];
            else if (k < 181) val = g_agg_a[node * AGGA_C + (k - 162)];
            else if (k < 184) {
                float dega = g_agg_a[node * AGGA_C + 19];
                val = (k == 181) ? dega : dega * ps[node * 2 + (k - 182)];
            } else if (k < 347) {
                float deg = g_agg_s[node * AGGS_C + 163];
                float inv = (deg > 0.f) ? (1.f / deg) : 0.f;
                val = g_agg_s[node * AGGS_C + (k - 184)] * inv;
            } else if (k < 350) {
                float m = (g_agg_s[node * AGGS_C + 163] > 0.f) ? 1.f : 0.f;
                val = (k == 347) ? m : m * ps[node * 2 + (k - 348)];
            } else if (k == 350) {
                val = 1.f;
            }
        }
        sFT[k * 36 + n] = val;
    }

    // ---- Phase 2: GEMM ----
    int c = tid & 31;     // column group: cols 4c..4c+3
    int r = tid >> 5;     // node group: nodes 4r..4r+3
    float acc[4][4];
#pragma unroll
    for (int n = 0; n < 4; n++)
#pragma unroll
        for (int j = 0; j < 4; j++) acc[n][j] = 0.f;

    const float4* Wf4 = (const float4*)g_Wf;
    float4* sW4 = (float4*)sW;

    for (int kc = 0; kc < KF / 32; kc++) {
        __syncthreads();
#pragma unroll
        for (int i = 0; i < 4; i++)
            sW4[tid + i * 256] = Wf4[kc * 1024 + tid + i * 256];
        __syncthreads();
#pragma unroll 8
        for (int kk = 0; kk < 32; kk++) {
            int k = kc * 32 + kk;
            float4 w  = sW4[kk * 32 + c];
            float4 fa = *(const float4*)&sFT[k * 36 + r * 4];
            acc[0][0] += fa.x * w.x; acc[0][1] += fa.x * w.y; acc[0][2] += fa.x * w.z; acc[0][3] += fa.x * w.w;
            acc[1][0] += fa.y * w.x; acc[1][1] += fa.y * w.y; acc[1][2] += fa.y * w.z; acc[1][3] += fa.y * w.w;
            acc[2][0] += fa.z * w.x; acc[2][1] += fa.z * w.y; acc[2][2] += fa.z * w.z; acc[2][3] += fa.z * w.w;
            acc[3][0] += fa.w * w.x; acc[3][1] += fa.w * w.y; acc[3][2] += fa.w * w.z; acc[3][3] += fa.w * w.w;
        }
    }

#pragma unroll
    for (int n = 0; n < 4; n++) {
        int node = base + r * 4 + n;
        if (node < N_S) {
            float4 o = make_float4(acc[n][0], acc[n][1], acc[n][2], acc[n][3]);
            *(float4*)&out[node * 128 + c * 4] = o;
        }
    }
}

extern "C" void kernel_launch(void* const* d_in, const int* in_sizes, int n_in,
                              void* d_out, int out_size) {
    const float* h       = (const float*)d_in[0];
    const float* x       = (const float*)d_in[1];
    const float* u       = (const float*)d_in[2];
    const float* ps      = (const float*)d_in[3];
    const float* pa      = (const float*)d_in[4];
    const float* dis_a   = (const float*)d_in[5];
    const float* dis_s   = (const float*)d_in[6];
    const int*   a2s_src = (const int*)d_in[7];
    const int*   a2s_dst = (const int*)d_in[8];
    const int*   s2s_src = (const int*)d_in[9];
    const int*   s2s_dst = (const int*)d_in[10];
    const float* Wu      = (const float*)d_in[11];
    const float* bu      = (const float*)d_in[12];
    const float* Wx      = (const float*)d_in[13];
    const float* bx      = (const float*)d_in[14];
    const float* Wupd    = (const float*)d_in[15];
    const float* bupd    = (const float*)d_in[16];
    float* out = (float*)d_out;

    const int smem_bytes = (KF * 36 + 32 * 128) * sizeof(float);   // 67072
    cudaFuncSetAttribute(fused_gemm, cudaFuncAttributeMaxDynamicSharedMemorySize, smem_bytes);

    zero_kernel<<<4096, 256>>>();
    scatter_a2s<<<(E_A + 255) / 256, 256>>>(u, pa, dis_a, a2s_src, a2s_dst);
    scatter_s2s<<<(E_S * 32 + 255) / 256, 256>>>(x, h, ps, dis_s, s2s_src, s2s_dst);
    fold_kernel<<<KF, 128>>>(Wu, bu, Wx, bx, Wupd, bupd);
    fused_gemm<<<(N_S + 31) / 32, 256, smem_bytes>>>(h, x, ps, out);
}